// round 7
// baseline (speedup 1.0000x reference)
#include <cuda_runtime.h>
#include <math.h>
#include <stdint.h>

#define BB 64
#define SS 512
#define FF 128
#define HH 512
#define G4 2048
#define NCTA 128
#define TPB 512

// Scratch (static device globals — no allocation at kernel_launch time)
__device__ float g_xg[(size_t)SS * BB * G4];    // [S][B][4H] input gates
__device__ float g_hist[(size_t)SS * BB * HH];  // [S][B][H] hidden states
__device__ unsigned g_flag[NCTA];               // per-producer step stamp

// packed dual-fp32 FMA (Blackwell f32x2)
#define FMA2(acc, a, h) asm("fma.rn.f32x2 %0, %1, %2, %0;" : "+l"(acc) : "l"(a), "l"(h))

__device__ __forceinline__ float rsum2(unsigned long long v) {
    float lo, hi;
    asm("mov.b64 {%0,%1}, %2;" : "=f"(lo), "=f"(hi) : "l"(v));
    return lo + hi;
}

#define CP16(dst, src) asm volatile("cp.async.cg.shared.global [%0], [%1], 16;" \
                                    :: "r"(dst), "l"(src))

__global__ void init_kernel() {
    int i = blockIdx.x * blockDim.x + threadIdx.x;
    if (i < NCTA) g_flag[i] = 0;
}

// ---------------------------------------------------------------------------
// x_gates GEMM: g_xg[m][g] = sum_f inputs[b,s,f]*W_ih[g,f] + b_ih[g]+b_hh[g]
// m = s*64+b. M=32768, N=2048, K=128. BM=BN=128, BK=16, 256 thr, 8x8, FMA2.
// ---------------------------------------------------------------------------
__global__ __launch_bounds__(256) void xg_kernel(
    const float* __restrict__ inp, const float* __restrict__ Wih,
    const float* __restrict__ bih, const float* __restrict__ bhh)
{
    __shared__ float As[16][132];
    __shared__ float Bs[16][132];
    const int gBase = blockIdx.x * 128;
    const int mBase = blockIdx.y * 128;
    const int t = threadIdx.x;
    const int tx = t & 15, ty = t >> 4;

    unsigned long long acc[8][4];
    #pragma unroll
    for (int i = 0; i < 8; i++)
        #pragma unroll
        for (int j = 0; j < 4; j++) acc[i][j] = 0ull;

    for (int k0 = 0; k0 < FF; k0 += 16) {
        #pragma unroll
        for (int it = 0; it < 2; it++) {
            int idx = t + (it << 8);
            int row = idx >> 2, c4 = idx & 3;
            int m = mBase + row;
            int b = m & 63, s = m >> 6;
            float4 v = *(const float4*)(inp + ((size_t)b * SS + s) * FF + k0 + (c4 << 2));
            As[c4 * 4 + 0][row] = v.x; As[c4 * 4 + 1][row] = v.y;
            As[c4 * 4 + 2][row] = v.z; As[c4 * 4 + 3][row] = v.w;
        }
        #pragma unroll
        for (int it = 0; it < 2; it++) {
            int idx = t + (it << 8);
            int row = idx >> 2, c4 = idx & 3;
            float4 v = *(const float4*)(Wih + (size_t)(gBase + row) * FF + k0 + (c4 << 2));
            Bs[c4 * 4 + 0][row] = v.x; Bs[c4 * 4 + 1][row] = v.y;
            Bs[c4 * 4 + 2][row] = v.z; Bs[c4 * 4 + 3][row] = v.w;
        }
        __syncthreads();
        #pragma unroll
        for (int kk = 0; kk < 16; kk++) {
            float a[8];
            *(float4*)(a)     = *(const float4*)&As[kk][ty * 8];
            *(float4*)(a + 4) = *(const float4*)&As[kk][ty * 8 + 4];
            ulonglong2 b01 = *(const ulonglong2*)&Bs[kk][tx * 8];
            ulonglong2 b23 = *(const ulonglong2*)&Bs[kk][tx * 8 + 4];
            #pragma unroll
            for (int i = 0; i < 8; i++) {
                unsigned long long a2;
                asm("mov.b64 %0, {%1, %1};" : "=l"(a2) : "f"(a[i]));
                FMA2(acc[i][0], a2, b01.x);
                FMA2(acc[i][1], a2, b01.y);
                FMA2(acc[i][2], a2, b23.x);
                FMA2(acc[i][3], a2, b23.y);
            }
        }
        __syncthreads();
    }

    float bias[8];
    #pragma unroll
    for (int j = 0; j < 8; j++) {
        int g = gBase + tx * 8 + j;
        bias[j] = bih[g] + bhh[g];
    }
    #pragma unroll
    for (int i = 0; i < 8; i++) {
        int m = mBase + ty * 8 + i;
        float f[8];
        #pragma unroll
        for (int jp = 0; jp < 4; jp++)
            asm("mov.b64 {%0,%1}, %2;" : "=f"(f[2*jp]), "=f"(f[2*jp+1]) : "l"(acc[i][jp]));
        float4 o0, o1;
        o0.x = f[0] + bias[0]; o0.y = f[1] + bias[1];
        o0.z = f[2] + bias[2]; o0.w = f[3] + bias[3];
        o1.x = f[4] + bias[4]; o1.y = f[5] + bias[5];
        o1.z = f[6] + bias[6]; o1.w = f[7] + bias[7];
        *(float4*)(g_xg + (size_t)m * G4 + gBase + tx * 8)     = o0;
        *(float4*)(g_xg + (size_t)m * G4 + gBase + tx * 8 + 4) = o1;
    }
}

// ---------------------------------------------------------------------------
// Persistent LSTM. 128 CTAs = 32 j-groups x 4 b-groups.
// Per-producer step-stamped flags: consumer warp-pair kq waits only for the
// 4 producers of its 64-k slice (4 parallel poll lanes, coalesced line).
// Thread = (kq in 8, jl in 16, bq in 4): 4 gates x 4 batches x 64 k.
// SMEM (floats): ws 32768 | hs 16x516 | xg2 2x1024 | red 256x33
// ---------------------------------------------------------------------------
#define SM_HS   32768
#define SM_XG   41024
#define SM_RED  43072
#define SM_TOT  51520

__global__ __launch_bounds__(TPB, 1) void lstm_persist(const float* __restrict__ Whh)
{
    extern __shared__ float sm[];
    float* ws  = sm;
    float* hs  = sm + SM_HS;
    float* xg2 = sm + SM_XG;
    float* red = sm + SM_RED;

    const int t = threadIdx.x;
    const int w = t >> 5, l = t & 31;
    const int jgrp = blockIdx.x >> 2;
    const int bgrp = blockIdx.x & 3;
    const int jg0  = jgrp << 4;
    const int b0   = bgrp << 4;

    const int kq = w >> 1;                     // 0..7
    const int jl = (l & 7) | ((w & 1) << 3);   // 0..15
    const int bq = l >> 3;                     // 0..3
    const int k0 = kq << 6;
    const int k0w = k0 + ((w & 1) << 5);       // this warp's 32-col h slice

    // Load W slice once: ws[row=jl*4+g][k], granule swizzle ^(jl&7)
    for (int i = t; i < 64 * 128; i += TPB) {
        int row = i >> 7, g16 = i & 127;
        int jr = row >> 2, gr = row & 3;
        int pg = g16 ^ (jr & 7);
        *(float4*)&ws[(row << 9) + (pg << 2)] =
            *(const float4*)&Whh[((size_t)(gr * HH + jg0 + jr) << 9) + (g16 << 2)];
    }

    // Prefetch xg(0): thread (bi,g,j4) -> xg2[(g*16+bi)*16 + j4*4]
    if (t < 256) {
        int bi = t >> 4, cc = t & 15;
        int g = cc >> 2, j4 = cc & 3;
        const float* src = g_xg + (size_t)(b0 + bi) * G4 + g * HH + jg0 + (j4 << 2);
        uint32_t d = (uint32_t)__cvta_generic_to_shared(
            &xg2[((g << 4) + bi) * 16 + (j4 << 2)]);
        CP16(d, src);
        asm volatile("cp.async.commit_group;");
    }
    __syncthreads();

    const float* wq0 = ws + ((jl * 4 + 0) << 9);
    const float* wq1 = ws + ((jl * 4 + 1) << 9);
    const float* wq2 = ws + ((jl * 4 + 2) << 9);
    const float* wq3 = ws + ((jl * 4 + 3) << 9);
    const int xr = (jl & 7) << 2;

    float c = 0.f;

    for (int s = 0; s < SS; s++) {
        // Prefetch xg(s+1)
        if (t < 256 && s + 1 < SS) {
            int bi = t >> 4, cc = t & 15;
            int g = cc >> 2, j4 = cc & 3;
            const float* src = g_xg +
                (size_t)((s + 1) * BB + b0 + bi) * G4 + g * HH + jg0 + (j4 << 2);
            uint32_t d = (uint32_t)__cvta_generic_to_shared(
                &xg2[(((s + 1) & 1) << 10) + ((g << 4) + bi) * 16 + (j4 << 2)]);
            CP16(d, src);
            asm volatile("cp.async.commit_group;");
        }

        if (s > 0) {
            // Wait only for this pair's 4 producers (parallel poll, one line)
            if (l < 4) {
                const unsigned* fa = g_flag + (bgrp << 5) + (kq << 2) + l;
                unsigned v;
                do {
                    asm volatile("ld.acquire.gpu.global.u32 %0, [%1];"
                                 : "=r"(v) : "l"(fa) : "memory");
                } while (v < (unsigned)s);
            }
            __syncwarp();

            // per-warp h slice: 16 batches x 32 k-cols
            {
                const float* hp = g_hist + ((size_t)(s - 1) << 15);
                #pragma unroll
                for (int it = 0; it < 4; it++) {
                    int idx = (it << 5) + l;
                    int r = idx >> 3, c4 = idx & 7;
                    int col = k0w + (c4 << 2);
                    uint32_t d = (uint32_t)__cvta_generic_to_shared(&hs[r * 516 + col]);
                    CP16(d, hp + (((size_t)(b0 + r)) << 9) + col);
                }
                asm volatile("cp.async.commit_group;");
                asm volatile("cp.async.wait_group 0;");
                asm volatile("bar.sync %0, 64;" :: "r"(kq + 1));
            }

            unsigned long long A0[4], A1[4], A2[4], A3[4];
            #pragma unroll
            for (int i = 0; i < 4; i++) { A0[i] = 0; A1[i] = 0; A2[i] = 0; A3[i] = 0; }

            #pragma unroll 4
            for (int k = k0; k < k0 + 64; k += 4) {
                int kx = k ^ xr;
                ulonglong2 w0 = *(const ulonglong2*)(wq0 + kx);
                ulonglong2 w1 = *(const ulonglong2*)(wq1 + kx);
                ulonglong2 w2 = *(const ulonglong2*)(wq2 + kx);
                ulonglong2 w3 = *(const ulonglong2*)(wq3 + kx);
                #pragma unroll
                for (int i = 0; i < 4; i++) {
                    ulonglong2 hv = *(const ulonglong2*)(hs + (i * 4 + bq) * 516 + k);
                    FMA2(A0[i], w0.x, hv.x); FMA2(A0[i], w0.y, hv.y);
                    FMA2(A1[i], w1.x, hv.x); FMA2(A1[i], w1.y, hv.y);
                    FMA2(A2[i], w2.x, hv.x); FMA2(A2[i], w2.y, hv.y);
                    FMA2(A3[i], w3.x, hv.x); FMA2(A3[i], w3.y, hv.y);
                }
            }
            // partials: red[(b*16+j)*33 + kq*4+g]
            const int rr = kq << 2;
            #pragma unroll
            for (int i = 0; i < 4; i++) {
                int base = ((i * 4 + bq) * 16 + jl) * 33 + rr;
                red[base + 0] = rsum2(A0[i]);
                red[base + 1] = rsum2(A1[i]);
                red[base + 2] = rsum2(A2[i]);
                red[base + 3] = rsum2(A3[i]);
            }
        } else {
            if (t < 256) asm volatile("cp.async.wait_group 1;");
        }
        __syncthreads();

        if (t < 256) {
            const int jo = t & 15, bo = t >> 4;
            const float* xb = xg2 + ((s & 1) << 10);
            float a0 = xb[       (bo << 4) + jo];
            float a1 = xb[256 +  (bo << 4) + jo];
            float a2 = xb[512 +  (bo << 4) + jo];
            float a3 = xb[768 +  (bo << 4) + jo];
            if (s > 0) {
                const float* rp = red + ((bo << 4) + jo) * 33;
                #pragma unroll
                for (int q = 0; q < 8; q++) {
                    a0 += rp[q * 4 + 0];
                    a1 += rp[q * 4 + 1];
                    a2 += rp[q * 4 + 2];
                    a3 += rp[q * 4 + 3];
                }
            }
            float ig = 1.f / (1.f + __expf(-a0));
            float fg = 1.f / (1.f + __expf(-a1));
            float gg = 2.f / (1.f + __expf(-2.f * a2)) - 1.f;
            float og = 1.f / (1.f + __expf(-a3));
            c = fg * c + ig * gg;
            float th = 2.f / (1.f + __expf(-2.f * c)) - 1.f;
            g_hist[((size_t)(s * BB + b0 + bo) << 9) + jg0 + jo] = og * th;
        }
        __syncthreads();
        if (t == 0)
            asm volatile("st.release.gpu.global.u32 [%0], %1;"
                         :: "l"(g_flag + (bgrp << 5) + jgrp), "r"((unsigned)(s + 1))
                         : "memory");
    }
}

// ---------------------------------------------------------------------------
// Output GEMM: out[b][s][f] = sum_j hist[s][b][j]*W_out[f][j] + b_out[f]
// ---------------------------------------------------------------------------
__global__ __launch_bounds__(256) void out_kernel(
    const float* __restrict__ Wout, const float* __restrict__ bout,
    float* __restrict__ out)
{
    __shared__ float As[32][68];
    __shared__ float Bs[32][68];
    const int fBase = blockIdx.x * 64;
    const int mBase = blockIdx.y * 64;
    const int t = threadIdx.x;
    const int tx = t & 15, ty = t >> 4;

    float acc[4][4] = {};

    for (int k0 = 0; k0 < HH; k0 += 32) {
        #pragma unroll
        for (int it = 0; it < 2; it++) {
            int idx = t + it * 256;
            int row = idx >> 3, vec = idx & 7;
            float4 v = *(const float4*)(g_hist + (size_t)(mBase + row) * HH + k0 + vec * 4);
            As[vec * 4 + 0][row] = v.x; As[vec * 4 + 1][row] = v.y;
            As[vec * 4 + 2][row] = v.z; As[vec * 4 + 3][row] = v.w;
        }
        #pragma unroll
        for (int it = 0; it < 2; it++) {
            int idx = t + it * 256;
            int row = idx >> 3, vec = idx & 7;
            float4 v = *(const float4*)(Wout + (size_t)(fBase + row) * HH + k0 + vec * 4);
            Bs[vec * 4 + 0][row] = v.x; Bs[vec * 4 + 1][row] = v.y;
            Bs[vec * 4 + 2][row] = v.z; Bs[vec * 4 + 3][row] = v.w;
        }
        __syncthreads();
        #pragma unroll
        for (int kk = 0; kk < 32; kk++) {
            float a[4], b[4];
            *(float4*)a = *(const float4*)&As[kk][ty * 4];
            *(float4*)b = *(const float4*)&Bs[kk][tx * 4];
            #pragma unroll
            for (int i = 0; i < 4; i++)
                #pragma unroll
                for (int jj = 0; jj < 4; jj++)
                    acc[i][jj] += a[i] * b[jj];
        }
        __syncthreads();
    }

    float bias[4];
    #pragma unroll
    for (int jj = 0; jj < 4; jj++) bias[jj] = bout[fBase + tx * 4 + jj];

    #pragma unroll
    for (int i = 0; i < 4; i++) {
        int m = mBase + ty * 4 + i;
        int b = m & 63, s = m >> 6;
        float4 o;
        o.x = acc[i][0] + bias[0];
        o.y = acc[i][1] + bias[1];
        o.z = acc[i][2] + bias[2];
        o.w = acc[i][3] + bias[3];
        *(float4*)(out + ((size_t)b * SS + s) * FF + fBase + tx * 4) = o;
    }
}

extern "C" void kernel_launch(void* const* d_in, const int* in_sizes, int n_in,
                              void* d_out, int out_size)
{
    const float* inp  = (const float*)d_in[0];
    const float* Wih  = (const float*)d_in[1];
    const float* Whh  = (const float*)d_in[2];
    const float* bih  = (const float*)d_in[3];
    const float* bhh  = (const float*)d_in[4];
    const float* Wout = (const float*)d_in[5];
    const float* bout = (const float*)d_in[6];
    float* out = (float*)d_out;

    const int smem_bytes = SM_TOT * 4;  // 206,080 B
    cudaFuncSetAttribute(lstm_persist,
                         cudaFuncAttributeMaxDynamicSharedMemorySize, smem_bytes);

    init_kernel<<<1, 256>>>();
    xg_kernel<<<dim3(G4 / 128, (SS * BB) / 128), 256>>>(inp, Wih, bih, bhh);
    lstm_persist<<<NCTA, TPB, smem_bytes>>>(Whh);
    out_kernel<<<dim3(FF / 64, (SS * BB) / 64), 256>>>(Wout, bout, out);
}

// round 8
// speedup vs baseline: 1.7774x; 1.7774x over previous
#include <cuda_runtime.h>
#include <math.h>
#include <stdint.h>

#define BB 64
#define SS 512
#define FF 128
#define HH 512
#define G4 2048
#define NCTA 128          // persist CTAs
#define NOUT 20           // out-role CTAs
#define NCTAG 32          // CTAs per b-group barrier
#define TPB 512

// Scratch (static device globals — no allocation at kernel_launch time)
__device__ float g_xg[(size_t)SS * BB * G4];    // [S][B][4H] input gates
__device__ float g_hist[(size_t)SS * BB * HH];  // [S][B][H] hidden states
__device__ unsigned g_cnt[4 * SS];              // per-(bgroup,step) counters

// packed dual-fp32 FMA (Blackwell f32x2)
#define FMA2(acc, a, h) asm("fma.rn.f32x2 %0, %1, %2, %0;" : "+l"(acc) : "l"(a), "l"(h))

__device__ __forceinline__ float rsum2(unsigned long long v) {
    float lo, hi;
    asm("mov.b64 {%0,%1}, %2;" : "=f"(lo), "=f"(hi) : "l"(v));
    return lo + hi;
}

#define CP16(dst, src) asm volatile("cp.async.cg.shared.global [%0], [%1], 16;" \
                                    :: "r"(dst), "l"(src))

__global__ void init_kernel() {
    int i = blockIdx.x * blockDim.x + threadIdx.x;
    if (i < 4 * SS) g_cnt[i] = 0;
}

// ---------------------------------------------------------------------------
// x_gates GEMM: g_xg[m][g] = sum_f inputs[b,s,f]*W_ih[g,f] + b_ih[g]+b_hh[g]
// m = s*64+b. M=32768, N=2048, K=128. BM=BN=128, BK=16, 256 thr, 8x8, FMA2.
// ---------------------------------------------------------------------------
__global__ __launch_bounds__(256) void xg_kernel(
    const float* __restrict__ inp, const float* __restrict__ Wih,
    const float* __restrict__ bih, const float* __restrict__ bhh)
{
    __shared__ float As[16][132];
    __shared__ float Bs[16][132];
    const int gBase = blockIdx.x * 128;
    const int mBase = blockIdx.y * 128;
    const int t = threadIdx.x;
    const int tx = t & 15, ty = t >> 4;

    unsigned long long acc[8][4];
    #pragma unroll
    for (int i = 0; i < 8; i++)
        #pragma unroll
        for (int j = 0; j < 4; j++) acc[i][j] = 0ull;

    for (int k0 = 0; k0 < FF; k0 += 16) {
        #pragma unroll
        for (int it = 0; it < 2; it++) {
            int idx = t + (it << 8);
            int row = idx >> 2, c4 = idx & 3;
            int m = mBase + row;
            int b = m & 63, s = m >> 6;
            float4 v = *(const float4*)(inp + ((size_t)b * SS + s) * FF + k0 + (c4 << 2));
            As[c4 * 4 + 0][row] = v.x; As[c4 * 4 + 1][row] = v.y;
            As[c4 * 4 + 2][row] = v.z; As[c4 * 4 + 3][row] = v.w;
        }
        #pragma unroll
        for (int it = 0; it < 2; it++) {
            int idx = t + (it << 8);
            int row = idx >> 2, c4 = idx & 3;
            float4 v = *(const float4*)(Wih + (size_t)(gBase + row) * FF + k0 + (c4 << 2));
            Bs[c4 * 4 + 0][row] = v.x; Bs[c4 * 4 + 1][row] = v.y;
            Bs[c4 * 4 + 2][row] = v.z; Bs[c4 * 4 + 3][row] = v.w;
        }
        __syncthreads();
        #pragma unroll
        for (int kk = 0; kk < 16; kk++) {
            float a[8];
            *(float4*)(a)     = *(const float4*)&As[kk][ty * 8];
            *(float4*)(a + 4) = *(const float4*)&As[kk][ty * 8 + 4];
            ulonglong2 b01 = *(const ulonglong2*)&Bs[kk][tx * 8];
            ulonglong2 b23 = *(const ulonglong2*)&Bs[kk][tx * 8 + 4];
            #pragma unroll
            for (int i = 0; i < 8; i++) {
                unsigned long long a2;
                asm("mov.b64 %0, {%1, %1};" : "=l"(a2) : "f"(a[i]));
                FMA2(acc[i][0], a2, b01.x);
                FMA2(acc[i][1], a2, b01.y);
                FMA2(acc[i][2], a2, b23.x);
                FMA2(acc[i][3], a2, b23.y);
            }
        }
        __syncthreads();
    }

    float bias[8];
    #pragma unroll
    for (int j = 0; j < 8; j++) {
        int g = gBase + tx * 8 + j;
        bias[j] = bih[g] + bhh[g];
    }
    #pragma unroll
    for (int i = 0; i < 8; i++) {
        int m = mBase + ty * 8 + i;
        float f[8];
        #pragma unroll
        for (int jp = 0; jp < 4; jp++)
            asm("mov.b64 {%0,%1}, %2;" : "=f"(f[2*jp]), "=f"(f[2*jp+1]) : "l"(acc[i][jp]));
        float4 o0, o1;
        o0.x = f[0] + bias[0]; o0.y = f[1] + bias[1];
        o0.z = f[2] + bias[2]; o0.w = f[3] + bias[3];
        o1.x = f[4] + bias[4]; o1.y = f[5] + bias[5];
        o1.z = f[6] + bias[6]; o1.w = f[7] + bias[7];
        *(float4*)(g_xg + (size_t)m * G4 + gBase + tx * 8)     = o0;
        *(float4*)(g_xg + (size_t)m * G4 + gBase + tx * 8 + 4) = o1;
    }
}

// ---------------------------------------------------------------------------
// Fused persistent kernel, grid = 148 CTAs:
//   blockIdx.x < 128 : LSTM persist role (32 j-groups x 4 b-groups)
//   blockIdx.x >= 128: out-projection role, consumes per-step counters and
//                      computes out[s] = h[s] @ W_out^T in persist's shadow.
// SMEM (floats): ws 32768 | hs 16x516 | xg2 2x1024 | red 256x33
// ---------------------------------------------------------------------------
#define SM_HS   32768
#define SM_XG   41024
#define SM_RED  43072
#define SM_TOT  51520

__global__ __launch_bounds__(TPB, 1) void lstm_persist(
    const float* __restrict__ Whh, const float* __restrict__ Wout,
    const float* __restrict__ bout, float* __restrict__ out)
{
    extern __shared__ float sm[];
    const int t = threadIdx.x;

    if (blockIdx.x >= NCTA) {
        // ------------------- out-projection role -------------------
        float* As = sm;                 // [32][68]
        float* Bs = sm + 32 * 68;       // [32][68]
        const int o = blockIdx.x - NCTA;            // 0..19
        const int tx = t & 31, ty = t >> 5;         // f-pair, m-quad

        for (int tt = o; tt < 2 * SS; tt += NOUT) {
            const int s = tt >> 1;
            const int fBase = (tt & 1) << 6;

            // wait for all 4 b-groups of step s
            if (t < 4) {
                const unsigned* ca = g_cnt + t * SS + s;
                unsigned v;
                do {
                    asm volatile("ld.acquire.gpu.global.u32 %0, [%1];"
                                 : "=r"(v) : "l"(ca) : "memory");
                } while (v < NCTAG);
            }
            __syncthreads();

            float acc[4][2] = {};
            const float* hb = g_hist + ((size_t)s << 15);   // h rows for this s

            for (int k0 = 0; k0 < HH; k0 += 32) {
                {   // 512 threads load 64 rows x 32 k of h (1 float4 each)
                    int row = t >> 3, c4 = t & 7;
                    float4 v = *(const float4*)(hb + ((size_t)row << 9) + k0 + (c4 << 2));
                    As[(c4 * 4 + 0) * 68 + row] = v.x;
                    As[(c4 * 4 + 1) * 68 + row] = v.y;
                    As[(c4 * 4 + 2) * 68 + row] = v.z;
                    As[(c4 * 4 + 3) * 68 + row] = v.w;
                }
                {   // 64 rows x 32 k of W_out
                    int row = t >> 3, c4 = t & 7;
                    float4 v = *(const float4*)(Wout +
                        (size_t)(fBase + row) * HH + k0 + (c4 << 2));
                    Bs[(c4 * 4 + 0) * 68 + row] = v.x;
                    Bs[(c4 * 4 + 1) * 68 + row] = v.y;
                    Bs[(c4 * 4 + 2) * 68 + row] = v.z;
                    Bs[(c4 * 4 + 3) * 68 + row] = v.w;
                }
                __syncthreads();
                #pragma unroll
                for (int kk = 0; kk < 32; kk++) {
                    float a[4], b[2];
                    *(float4*)a = *(const float4*)&As[kk * 68 + ty * 4];
                    b[0] = Bs[kk * 68 + tx * 2];
                    b[1] = Bs[kk * 68 + tx * 2 + 1];
                    #pragma unroll
                    for (int i = 0; i < 4; i++) {
                        acc[i][0] += a[i] * b[0];
                        acc[i][1] += a[i] * b[1];
                    }
                }
                __syncthreads();
            }

            float bias0 = bout[fBase + tx * 2];
            float bias1 = bout[fBase + tx * 2 + 1];
            #pragma unroll
            for (int i = 0; i < 4; i++) {
                int b = ty * 4 + i;           // batch
                float2 ov;
                ov.x = acc[i][0] + bias0;
                ov.y = acc[i][1] + bias1;
                *(float2*)(out + ((size_t)b * SS + s) * FF + fBase + tx * 2) = ov;
            }
        }
        return;
    }

    // ---------------------- LSTM persist role ----------------------
    float* ws  = sm;
    float* hs  = sm + SM_HS;
    float* xg2 = sm + SM_XG;
    float* red = sm + SM_RED;

    const int w = t >> 5, l = t & 31;
    const int jgrp = blockIdx.x >> 2;
    const int bgrp = blockIdx.x & 3;
    const int jg0  = jgrp << 4;
    const int b0   = bgrp << 4;

    const int kq = w >> 1;                     // 0..7
    const int jl = (l & 7) | ((w & 1) << 3);   // 0..15
    const int bq = l >> 3;                     // 0..3
    const int k0 = kq << 6;
    const int k0w = k0 + ((w & 1) << 5);       // this warp's 32-col h slice

    // Load W slice once: ws[row=jl*4+g][k], granule swizzle ^(jl&7)
    for (int i = t; i < 64 * 128; i += TPB) {
        int row = i >> 7, g16 = i & 127;
        int jr = row >> 2, gr = row & 3;
        int pg = g16 ^ (jr & 7);
        *(float4*)&ws[(row << 9) + (pg << 2)] =
            *(const float4*)&Whh[((size_t)(gr * HH + jg0 + jr) << 9) + (g16 << 2)];
    }

    // Prefetch xg(0) and xg(1) (warps 0-7), separate commit groups
    if (t < 256) {
        int bi = t >> 4, cc = t & 15;
        int g = cc >> 2, j4 = cc & 3;
        {
            const float* src = g_xg + (size_t)(b0 + bi) * G4 + g * HH + jg0 + (j4 << 2);
            uint32_t d = (uint32_t)__cvta_generic_to_shared(
                &xg2[((g << 4) + bi) * 16 + (j4 << 2)]);
            CP16(d, src);
            asm volatile("cp.async.commit_group;");
        }
        {
            const float* src = g_xg + (size_t)(BB + b0 + bi) * G4 + g * HH + jg0 + (j4 << 2);
            uint32_t d = (uint32_t)__cvta_generic_to_shared(
                &xg2[1024 + ((g << 4) + bi) * 16 + (j4 << 2)]);
            CP16(d, src);
            asm volatile("cp.async.commit_group;");
        }
    }
    __syncthreads();

    const float* wq0 = ws + ((jl * 4 + 0) << 9);
    const float* wq1 = ws + ((jl * 4 + 1) << 9);
    const float* wq2 = ws + ((jl * 4 + 2) << 9);
    const float* wq3 = ws + ((jl * 4 + 3) << 9);
    const int xr = (jl & 7) << 2;

    float c = 0.f;

    for (int s = 0; s < SS; s++) {
        if (s > 0) {
            if (t == 0) {
                unsigned v;
                const unsigned* ca = g_cnt + bgrp * SS + (s - 1);
                do {
                    asm volatile("ld.acquire.gpu.global.u32 %0, [%1];"
                                 : "=r"(v) : "l"(ca) : "memory");
                } while (v < NCTAG);
            }
            __syncthreads();

            // per-warp h slice: 16 batches x 32 k-cols
            {
                const float* hp = g_hist + ((size_t)(s - 1) << 15);
                #pragma unroll
                for (int it = 0; it < 4; it++) {
                    int idx = (it << 5) + l;
                    int r = idx >> 3, c4 = idx & 7;
                    int col = k0w + (c4 << 2);
                    uint32_t d = (uint32_t)__cvta_generic_to_shared(&hs[r * 516 + col]);
                    CP16(d, hp + (((size_t)(b0 + r)) << 9) + col);
                }
                asm volatile("cp.async.commit_group;");
                asm volatile("cp.async.wait_group 0;");
                asm volatile("bar.sync %0, 64;" :: "r"(kq + 1));
            }

            // Prefetch xg(s+1) during compute (warps 0-7 only)
            if (t < 256 && s + 1 < SS) {
                int bi = t >> 4, cc = t & 15;
                int g = cc >> 2, j4 = cc & 3;
                const float* src = g_xg +
                    (size_t)((s + 1) * BB + b0 + bi) * G4 + g * HH + jg0 + (j4 << 2);
                uint32_t d = (uint32_t)__cvta_generic_to_shared(
                    &xg2[(((s + 1) & 1) << 10) + ((g << 4) + bi) * 16 + (j4 << 2)]);
                CP16(d, src);
                asm volatile("cp.async.commit_group;");
            }

            unsigned long long A0[4], A1[4], A2[4], A3[4];
            #pragma unroll
            for (int i = 0; i < 4; i++) { A0[i] = 0; A1[i] = 0; A2[i] = 0; A3[i] = 0; }

            #pragma unroll 4
            for (int k = k0; k < k0 + 64; k += 4) {
                int kx = k ^ xr;
                ulonglong2 w0 = *(const ulonglong2*)(wq0 + kx);
                ulonglong2 w1 = *(const ulonglong2*)(wq1 + kx);
                ulonglong2 w2 = *(const ulonglong2*)(wq2 + kx);
                ulonglong2 w3 = *(const ulonglong2*)(wq3 + kx);
                #pragma unroll
                for (int i = 0; i < 4; i++) {
                    ulonglong2 hv = *(const ulonglong2*)(hs + (i * 4 + bq) * 516 + k);
                    FMA2(A0[i], w0.x, hv.x); FMA2(A0[i], w0.y, hv.y);
                    FMA2(A1[i], w1.x, hv.x); FMA2(A1[i], w1.y, hv.y);
                    FMA2(A2[i], w2.x, hv.x); FMA2(A2[i], w2.y, hv.y);
                    FMA2(A3[i], w3.x, hv.x); FMA2(A3[i], w3.y, hv.y);
                }
            }
            // partials: red[(b*16+j)*33 + kq*4+g]
            const int rr = kq << 2;
            #pragma unroll
            for (int i = 0; i < 4; i++) {
                int base = ((i * 4 + bq) * 16 + jl) * 33 + rr;
                red[base + 0] = rsum2(A0[i]);
                red[base + 1] = rsum2(A1[i]);
                red[base + 2] = rsum2(A2[i]);
                red[base + 3] = rsum2(A3[i]);
            }
        } else {
            // xg(0) must be resident (xg(1) may still be in flight)
            if (t < 256) asm volatile("cp.async.wait_group 1;");
        }
        __syncthreads();

        if (t < 256) {
            const int jo = t & 15, bo = t >> 4;
            const float* xb = xg2 + ((s & 1) << 10);
            float a0 = xb[       (bo << 4) + jo];
            float a1 = xb[256 +  (bo << 4) + jo];
            float a2 = xb[512 +  (bo << 4) + jo];
            float a3 = xb[768 +  (bo << 4) + jo];
            if (s > 0) {
                const float* rp = red + ((bo << 4) + jo) * 33;
                #pragma unroll
                for (int q = 0; q < 8; q++) {
                    a0 += rp[q * 4 + 0];
                    a1 += rp[q * 4 + 1];
                    a2 += rp[q * 4 + 2];
                    a3 += rp[q * 4 + 3];
                }
            }
            float ig = 1.f / (1.f + __expf(-a0));
            float fg = 1.f / (1.f + __expf(-a1));
            float gg = 2.f / (1.f + __expf(-2.f * a2)) - 1.f;
            float og = 1.f / (1.f + __expf(-a3));
            c = fg * c + ig * gg;
            float th = 2.f / (1.f + __expf(-2.f * c)) - 1.f;
            g_hist[((size_t)(s * BB + b0 + bo) << 9) + jg0 + jo] = og * th;
        }
        __syncthreads();
        if (t == 0)
            asm volatile("red.release.gpu.global.add.u32 [%0], %1;"
                         :: "l"(g_cnt + bgrp * SS + s), "r"(1u) : "memory");
    }
}

extern "C" void kernel_launch(void* const* d_in, const int* in_sizes, int n_in,
                              void* d_out, int out_size)
{
    const float* inp  = (const float*)d_in[0];
    const float* Wih  = (const float*)d_in[1];
    const float* Whh  = (const float*)d_in[2];
    const float* bih  = (const float*)d_in[3];
    const float* bhh  = (const float*)d_in[4];
    const float* Wout = (const float*)d_in[5];
    const float* bout = (const float*)d_in[6];
    float* out = (float*)d_out;

    const int smem_bytes = SM_TOT * 4;  // 206,080 B
    cudaFuncSetAttribute(lstm_persist,
                         cudaFuncAttributeMaxDynamicSharedMemorySize, smem_bytes);

    init_kernel<<<8, 256>>>();
    xg_kernel<<<dim3(G4 / 128, (SS * BB) / 128), 256>>>(inp, Wih, bih, bhh);
    lstm_persist<<<NCTA + NOUT, TPB, smem_bytes>>>(Whh, Wout, bout, out);
}